// round 15
// baseline (speedup 1.0000x reference)
#include <cuda_runtime.h>
#include <cuda_bf16.h>
#include <cstdint>

// GruDirection3d forward wavefront:
//   out[d,y,x] = z*h_tilde + (1-z)*out[d-1,y-1,x-1],  border -> h0
//
// R15 = R11 frame (512 thr = 2 independent 256-thread named-barrier domains,
// 2 volumes/CTA, 96 CTAs = one wave, float4 + 33-stride smem tile, depth-4
// register prefetch) + L2 residency via createpolicy/cache_hint (the direct
// .L2::evict_last modifier is rejected on .v4.f32 by this ptxas):
//   - z/h_tilde loads: ld.global.nc.L2::cache_hint with evict_last policy
//     (50.3MB fits in 126MB L2 -> resident across graph replays)
//   - output stores:   st.global.L2::cache_hint with evict_first policy
// Rationale: R1..R13 all pin at ~12.7-13.1us = 75.5MB through the memory
// system; the only remaining lever is removing DRAM traffic.

#define PLANE4 256      // float4 per 32x32 plane
#define STRIDE 33
#define TILE   (STRIDE * 33)
#define PD     4

__device__ __forceinline__ float4 ldg_pol(const float4* p, uint64_t pol) {
    float4 v;
    asm volatile("ld.global.nc.L2::cache_hint.v4.f32 {%0,%1,%2,%3}, [%4], %5;"
                 : "=f"(v.x), "=f"(v.y), "=f"(v.z), "=f"(v.w)
                 : "l"(p), "l"(pol));
    return v;
}
__device__ __forceinline__ void stg_pol(float4* p, float4 v, uint64_t pol) {
    asm volatile("st.global.L2::cache_hint.v4.f32 [%0], {%1,%2,%3,%4}, %5;"
                 :: "l"(p), "f"(v.x), "f"(v.y), "f"(v.z), "f"(v.w), "l"(pol)
                 : "memory");
}

__global__ __launch_bounds__(512, 1)
void gru3d_kernel(const float4* __restrict__ zv,
                  const float4* __restrict__ hv,
                  const float*  __restrict__ h0p,
                  float4*       __restrict__ ov)
{
    __shared__ float buf[2][2][TILE];   // [domain][phase][tile]

    uint64_t pol_keep, pol_stream;
    asm volatile("createpolicy.fractional.L2::evict_last.b64 %0, 1.0;"
                 : "=l"(pol_keep));
    asm volatile("createpolicy.fractional.L2::evict_first.b64 %0, 1.0;"
                 : "=l"(pol_stream));

    const float h0 = __ldg(h0p);
    const int tid = threadIdx.x;
    const int dom = tid >> 8;           // 0/1: which volume
    const int t   = tid & 255;

    #pragma unroll
    for (int i = tid; i < 2 * 2 * TILE; i += 512)
        (&buf[0][0][0])[i] = h0;

    const int y  = t >> 3;    // 0..31
    const int x4 = t & 7;     // 0..7

    const int vol = blockIdx.x * 2 + dom;
    const size_t base = (size_t)vol * (32 * PLANE4) + (size_t)(y * 8 + x4);
    const float4* zp = zv + base;
    const float4* hp = hv + base;
    float4*       op = ov + base;

    // Register prefetch: planes 0..PD-1 in flight (evict_last loads).
    float4 zb[PD], hb[PD];
    #pragma unroll
    for (int s = 0; s < PD; ++s) {
        zb[s] = ldg_pol(zp + (size_t)s * PLANE4, pol_keep);
        hb[s] = ldg_pol(hp + (size_t)s * PLANE4, pol_keep);
    }

    __syncthreads();   // tile init visible

    const int rbase = y * STRIDE + 4 * x4;
    const int wbase = (y + 1) * STRIDE + 4 * x4 + 1;
    const int bid = 1 + dom;            // named barrier id per domain

    #pragma unroll
    for (int d = 0; d < 32; ++d) {
        const int s = d & (PD - 1);
        const float4 zc = zb[s];
        const float4 hc = hb[s];

        if (d + PD < 32) {
            zb[s] = ldg_pol(zp + (size_t)(d + PD) * PLANE4, pol_keep);
            hb[s] = ldg_pol(hp + (size_t)(d + PD) * PLANE4, pol_keep);
        }

        const float* rb = &buf[dom][(d + 1) & 1][rbase];
        const float p0 = rb[0], p1 = rb[1], p2 = rb[2], p3 = rb[3];

        float4 o;
        o.x = fmaf(zc.x, hc.x - p0, p0);
        o.y = fmaf(zc.y, hc.y - p1, p1);
        o.z = fmaf(zc.z, hc.z - p2, p2);
        o.w = fmaf(zc.w, hc.w - p3, p3);

        float* wb = &buf[dom][d & 1][wbase];
        wb[0] = o.x; wb[1] = o.y; wb[2] = o.z; wb[3] = o.w;

        stg_pol(op + (size_t)d * PLANE4, o, pol_stream);

        asm volatile("bar.sync %0, 256;" :: "r"(bid) : "memory");
    }
}

extern "C" void kernel_launch(void* const* d_in, const int* in_sizes, int n_in,
                              void* d_out, int out_size)
{
    const float4* z  = (const float4*)d_in[0];
    const float4* ht = (const float4*)d_in[1];
    const float*  h0 = (const float*)d_in[2];
    float4* out = (float4*)d_out;

    const int n_volumes = out_size / (32 * PLANE4 * 4);   // B*C = 192
    gru3d_kernel<<<n_volumes / 2, 512>>>(z, ht, h0, out);
}